// round 1
// baseline (speedup 1.0000x reference)
#include <cuda_runtime.h>

#define RBLOCKS 1184
#define RTHREADS 256

// Per-block partial sums: layout [accumulator][block] for coalesced final read.
__device__ float g_part[5 * RBLOCKS];

struct Eig {
    float e1, e2;      // analytic evals (larger, smaller)
    float v1x, v1y;    // matched eigenvector for e1
    float v2x, v2y;    // matched eigenvector for e2
};

__device__ __forceinline__ Eig eig2(float a, float b, float d) {
    Eig o;
    float mean = 0.5f * (a + d);
    float diff = 0.5f * (a - d);
    float r2   = fmaf(diff, diff, b * b);
    float r    = (r2 > 0.0f) ? r2 * rsqrtf(r2) : 0.0f;   // sqrt(r2) via MUFU.RSQ
    o.e1 = mean + r;       // == lam_hi
    o.e2 = mean - r;       // == lam_lo
    float vx = b;
    float vy = o.e1 - a;   // lam_hi - a
    float n2 = fmaf(vx, vx, vy * vy);
    bool safe = (n2 > 1e-36f);
    float inv = safe ? rsqrtf(n2) : 0.0f;
    float vhx = safe ? vx * inv : 1.0f;
    float vhy = vy * inv;          // inv==0 in unsafe branch -> 0
    // argmin matching collapses: evals = [lam_lo, lam_hi].
    //  idx2: |lam_lo - e2| = 0 -> always column 0 = v_lo = (-vhy, vhx)
    //  idx1: |lam_hi - e1| = 0 unless r == 0 (tie -> column 0 = v_lo)
    o.v2x = -vhy; o.v2y = vhx;
    if (r > 0.0f) { o.v1x = vhx;  o.v1y = vhy; }
    else          { o.v1x = -vhy; o.v1y = vhx; }
    return o;
}

__device__ __forceinline__ void accum_row(float pa, float pb, float pd,
                                          float ta, float tb, float td,
                                          float& s0, float& s1, float& s2,
                                          float& s3, float& s4) {
    Eig p = eig2(pa, pb, pd);
    Eig t = eig2(ta, tb, td);
    float de1 = p.e1 - t.e1;  s0 = fmaf(de1, de1, s0);
    float de2 = p.e2 - t.e2;  s0 = fmaf(de2, de2, s0);
    float a1 = p.v1x - t.v1x; s1 = fmaf(a1, a1, s1);
    float a2 = p.v1y - t.v1y; s2 = fmaf(a2, a2, s2);
    float a3 = p.v2x - t.v2x; s3 = fmaf(a3, a3, s3);
    float a4 = p.v2y - t.v2y; s4 = fmaf(a4, a4, s4);
}

__global__ __launch_bounds__(RTHREADS)
void eigh_partial_kernel(const float4* __restrict__ pred4,
                         const float4* __restrict__ true4,
                         const float*  __restrict__ pred,
                         const float*  __restrict__ tru,
                         int ngroups, int B) {
    float s0 = 0.f, s1 = 0.f, s2 = 0.f, s3 = 0.f, s4 = 0.f;

    int stride = gridDim.x * blockDim.x;
    for (int g = blockIdx.x * blockDim.x + threadIdx.x; g < ngroups; g += stride) {
        // 4 rows = 12 floats = 3x float4, fully coalesced 16B loads
        float4 p0 = pred4[3 * g + 0];
        float4 p1 = pred4[3 * g + 1];
        float4 p2 = pred4[3 * g + 2];
        float4 t0 = true4[3 * g + 0];
        float4 t1 = true4[3 * g + 1];
        float4 t2 = true4[3 * g + 2];
        accum_row(p0.x, p0.y, p0.z,  t0.x, t0.y, t0.z,  s0, s1, s2, s3, s4);
        accum_row(p0.w, p1.x, p1.y,  t0.w, t1.x, t1.y,  s0, s1, s2, s3, s4);
        accum_row(p1.z, p1.w, p2.x,  t1.z, t1.w, t2.x,  s0, s1, s2, s3, s4);
        accum_row(p2.y, p2.z, p2.w,  t2.y, t2.z, t2.w,  s0, s1, s2, s3, s4);
    }

    // Tail rows (B % 4), handled by first threads of block 0 (B=4M -> none)
    int tail = B - 4 * ngroups;
    if (blockIdx.x == 0 && (int)threadIdx.x < tail) {
        int r = 4 * ngroups + (int)threadIdx.x;
        accum_row(pred[3 * r], pred[3 * r + 1], pred[3 * r + 2],
                  tru [3 * r], tru [3 * r + 1], tru [3 * r + 2],
                  s0, s1, s2, s3, s4);
    }

    // Deterministic block reduction: warp shuffle tree, then smem, then warp 0.
    __shared__ float sm[5][RTHREADS / 32];
    int lane = threadIdx.x & 31;
    int warp = threadIdx.x >> 5;
    #pragma unroll
    for (int off = 16; off > 0; off >>= 1) {
        s0 += __shfl_down_sync(0xffffffffu, s0, off);
        s1 += __shfl_down_sync(0xffffffffu, s1, off);
        s2 += __shfl_down_sync(0xffffffffu, s2, off);
        s3 += __shfl_down_sync(0xffffffffu, s3, off);
        s4 += __shfl_down_sync(0xffffffffu, s4, off);
    }
    if (lane == 0) {
        sm[0][warp] = s0; sm[1][warp] = s1; sm[2][warp] = s2;
        sm[3][warp] = s3; sm[4][warp] = s4;
    }
    __syncthreads();
    if (warp == 0) {
        const int nw = RTHREADS / 32;
        float v0 = (lane < nw) ? sm[0][lane] : 0.f;
        float v1 = (lane < nw) ? sm[1][lane] : 0.f;
        float v2 = (lane < nw) ? sm[2][lane] : 0.f;
        float v3 = (lane < nw) ? sm[3][lane] : 0.f;
        float v4 = (lane < nw) ? sm[4][lane] : 0.f;
        #pragma unroll
        for (int off = nw / 2; off > 0; off >>= 1) {
            v0 += __shfl_down_sync(0xffffffffu, v0, off);
            v1 += __shfl_down_sync(0xffffffffu, v1, off);
            v2 += __shfl_down_sync(0xffffffffu, v2, off);
            v3 += __shfl_down_sync(0xffffffffu, v3, off);
            v4 += __shfl_down_sync(0xffffffffu, v4, off);
        }
        if (lane == 0) {
            g_part[0 * RBLOCKS + blockIdx.x] = v0;
            g_part[1 * RBLOCKS + blockIdx.x] = v1;
            g_part[2 * RBLOCKS + blockIdx.x] = v2;
            g_part[3 * RBLOCKS + blockIdx.x] = v3;
            g_part[4 * RBLOCKS + blockIdx.x] = v4;
        }
    }
}

// One block, 5 warps; warp j reduces accumulator j in double (deterministic order).
__global__ __launch_bounds__(160)
void eigh_final_kernel(const float* __restrict__ w, float* __restrict__ out, int B) {
    __shared__ double sm[5];
    int warp = threadIdx.x >> 5;
    int lane = threadIdx.x & 31;
    double s = 0.0;
    for (int i = lane; i < RBLOCKS; i += 32)
        s += (double)g_part[warp * RBLOCKS + i];
    #pragma unroll
    for (int off = 16; off > 0; off >>= 1)
        s += __shfl_down_sync(0xffffffffu, s, off);
    if (lane == 0) sm[warp] = s;
    __syncthreads();
    if (threadIdx.x == 0) {
        double Bd = (double)B;
        double mse = (double)w[0] * sm[0] / (2.0 * Bd)
                   + (double)w[1] * sm[1] / Bd
                   + (double)w[2] * sm[2] / Bd
                   + (double)w[3] * sm[3] / Bd
                   + (double)w[4] * sm[4] / Bd;
        out[0] = (float)mse;
    }
}

extern "C" void kernel_launch(void* const* d_in, const int* in_sizes, int n_in,
                              void* d_out, int out_size) {
    const float* pred = (const float*)d_in[0];
    const float* tru  = (const float*)d_in[1];
    const float* w    = (const float*)d_in[2];
    float* out = (float*)d_out;

    int B = in_sizes[0] / 3;
    int ngroups = B / 4;

    eigh_partial_kernel<<<RBLOCKS, RTHREADS>>>(
        (const float4*)pred, (const float4*)tru, pred, tru, ngroups, B);
    eigh_final_kernel<<<1, 160>>>(w, out, B);
}

// round 2
// speedup vs baseline: 1.0236x; 1.0236x over previous
#include <cuda_runtime.h>

#define RBLOCKS 1184
#define RTHREADS 256

// Per-block partial sums: layout [accumulator][block] for coalesced final read.
__device__ float g_part[5 * RBLOCKS];

struct Eig {
    float e1, e2;      // analytic evals (larger, smaller)
    float v1x, v1y;    // matched eigenvector for e1
    float v2x, v2y;    // matched eigenvector for e2
};

__device__ __forceinline__ Eig eig2(float a, float b, float d) {
    Eig o;
    float mean = 0.5f * (a + d);
    float diff = 0.5f * (a - d);
    float r2   = fmaf(diff, diff, b * b);
    float r    = (r2 > 0.0f) ? r2 * rsqrtf(r2) : 0.0f;   // sqrt(r2) via MUFU.RSQ
    o.e1 = mean + r;       // == lam_hi
    o.e2 = mean - r;       // == lam_lo
    float vx = b;
    float vy = o.e1 - a;   // lam_hi - a
    float n2 = fmaf(vx, vx, vy * vy);
    bool safe = (n2 > 1e-36f);
    float inv = safe ? rsqrtf(n2) : 0.0f;
    float vhx = safe ? vx * inv : 1.0f;
    float vhy = vy * inv;          // inv==0 in unsafe branch -> 0
    // argmin matching collapses: evals = [lam_lo, lam_hi].
    //  idx2: |lam_lo - e2| = 0 -> always column 0 = v_lo = (-vhy, vhx)
    //  idx1: |lam_hi - e1| = 0 unless r == 0 (tie -> column 0 = v_lo)
    o.v2x = -vhy; o.v2y = vhx;
    if (r > 0.0f) { o.v1x = vhx;  o.v1y = vhy; }
    else          { o.v1x = -vhy; o.v1y = vhx; }
    return o;
}

__device__ __forceinline__ void accum_row(float pa, float pb, float pd,
                                          float ta, float tb, float td,
                                          float& s0, float& s1, float& s2,
                                          float& s3, float& s4) {
    Eig p = eig2(pa, pb, pd);
    Eig t = eig2(ta, tb, td);
    float de1 = p.e1 - t.e1;  s0 = fmaf(de1, de1, s0);
    float de2 = p.e2 - t.e2;  s0 = fmaf(de2, de2, s0);
    float a1 = p.v1x - t.v1x; s1 = fmaf(a1, a1, s1);
    float a2 = p.v1y - t.v1y; s2 = fmaf(a2, a2, s2);
    float a3 = p.v2x - t.v2x; s3 = fmaf(a3, a3, s3);
    float a4 = p.v2y - t.v2y; s4 = fmaf(a4, a4, s4);
}

__global__ __launch_bounds__(RTHREADS)
void eigh_partial_kernel(const float4* __restrict__ pred4,
                         const float4* __restrict__ true4,
                         const float*  __restrict__ pred,
                         const float*  __restrict__ tru,
                         int ngroups, int B) {
    float s0 = 0.f, s1 = 0.f, s2 = 0.f, s3 = 0.f, s4 = 0.f;

    int stride = gridDim.x * blockDim.x;
    for (int g = blockIdx.x * blockDim.x + threadIdx.x; g < ngroups; g += stride) {
        // 4 rows = 12 floats = 3x float4, fully coalesced 16B loads
        float4 p0 = pred4[3 * g + 0];
        float4 p1 = pred4[3 * g + 1];
        float4 p2 = pred4[3 * g + 2];
        float4 t0 = true4[3 * g + 0];
        float4 t1 = true4[3 * g + 1];
        float4 t2 = true4[3 * g + 2];
        accum_row(p0.x, p0.y, p0.z,  t0.x, t0.y, t0.z,  s0, s1, s2, s3, s4);
        accum_row(p0.w, p1.x, p1.y,  t0.w, t1.x, t1.y,  s0, s1, s2, s3, s4);
        accum_row(p1.z, p1.w, p2.x,  t1.z, t1.w, t2.x,  s0, s1, s2, s3, s4);
        accum_row(p2.y, p2.z, p2.w,  t2.y, t2.z, t2.w,  s0, s1, s2, s3, s4);
    }

    // Tail rows (B % 4), handled by first threads of block 0 (B=4M -> none)
    int tail = B - 4 * ngroups;
    if (blockIdx.x == 0 && (int)threadIdx.x < tail) {
        int r = 4 * ngroups + (int)threadIdx.x;
        accum_row(pred[3 * r], pred[3 * r + 1], pred[3 * r + 2],
                  tru [3 * r], tru [3 * r + 1], tru [3 * r + 2],
                  s0, s1, s2, s3, s4);
    }

    // Deterministic block reduction: warp shuffle tree, then smem, then warp 0.
    __shared__ float sm[5][RTHREADS / 32];
    int lane = threadIdx.x & 31;
    int warp = threadIdx.x >> 5;
    #pragma unroll
    for (int off = 16; off > 0; off >>= 1) {
        s0 += __shfl_down_sync(0xffffffffu, s0, off);
        s1 += __shfl_down_sync(0xffffffffu, s1, off);
        s2 += __shfl_down_sync(0xffffffffu, s2, off);
        s3 += __shfl_down_sync(0xffffffffu, s3, off);
        s4 += __shfl_down_sync(0xffffffffu, s4, off);
    }
    if (lane == 0) {
        sm[0][warp] = s0; sm[1][warp] = s1; sm[2][warp] = s2;
        sm[3][warp] = s3; sm[4][warp] = s4;
    }
    __syncthreads();
    if (warp == 0) {
        const int nw = RTHREADS / 32;
        float v0 = (lane < nw) ? sm[0][lane] : 0.f;
        float v1 = (lane < nw) ? sm[1][lane] : 0.f;
        float v2 = (lane < nw) ? sm[2][lane] : 0.f;
        float v3 = (lane < nw) ? sm[3][lane] : 0.f;
        float v4 = (lane < nw) ? sm[4][lane] : 0.f;
        #pragma unroll
        for (int off = nw / 2; off > 0; off >>= 1) {
            v0 += __shfl_down_sync(0xffffffffu, v0, off);
            v1 += __shfl_down_sync(0xffffffffu, v1, off);
            v2 += __shfl_down_sync(0xffffffffu, v2, off);
            v3 += __shfl_down_sync(0xffffffffu, v3, off);
            v4 += __shfl_down_sync(0xffffffffu, v4, off);
        }
        if (lane == 0) {
            g_part[0 * RBLOCKS + blockIdx.x] = v0;
            g_part[1 * RBLOCKS + blockIdx.x] = v1;
            g_part[2 * RBLOCKS + blockIdx.x] = v2;
            g_part[3 * RBLOCKS + blockIdx.x] = v3;
            g_part[4 * RBLOCKS + blockIdx.x] = v4;
        }
    }
}

// One block, 5 warps; warp j reduces accumulator j in double (deterministic order).
__global__ __launch_bounds__(160)
void eigh_final_kernel(const float* __restrict__ w, float* __restrict__ out, int B) {
    __shared__ double sm[5];
    int warp = threadIdx.x >> 5;
    int lane = threadIdx.x & 31;
    double s = 0.0;
    for (int i = lane; i < RBLOCKS; i += 32)
        s += (double)g_part[warp * RBLOCKS + i];
    #pragma unroll
    for (int off = 16; off > 0; off >>= 1)
        s += __shfl_down_sync(0xffffffffu, s, off);
    if (lane == 0) sm[warp] = s;
    __syncthreads();
    if (threadIdx.x == 0) {
        double Bd = (double)B;
        double mse = (double)w[0] * sm[0] / (2.0 * Bd)
                   + (double)w[1] * sm[1] / Bd
                   + (double)w[2] * sm[2] / Bd
                   + (double)w[3] * sm[3] / Bd
                   + (double)w[4] * sm[4] / Bd;
        out[0] = (float)mse;
    }
}

extern "C" void kernel_launch(void* const* d_in, const int* in_sizes, int n_in,
                              void* d_out, int out_size) {
    const float* pred = (const float*)d_in[0];
    const float* tru  = (const float*)d_in[1];
    const float* w    = (const float*)d_in[2];
    float* out = (float*)d_out;

    int B = in_sizes[0] / 3;
    int ngroups = B / 4;

    eigh_partial_kernel<<<RBLOCKS, RTHREADS>>>(
        (const float4*)pred, (const float4*)tru, pred, tru, ngroups, B);
    eigh_final_kernel<<<1, 160>>>(w, out, B);
}